// round 1
// baseline (speedup 1.0000x reference)
#include <cuda_runtime.h>
#include <cuda_bf16.h>
#include <mma.h>

using namespace nvcuda;
typedef __nv_bfloat16 bf16;

#define NB    32
#define NENC  512
#define DSEQ  1024
#define NHEAD 8
#define HDIM  128
#define MROWS (NB*NENC)      /* 16384 */
#define NQKV  (3*DSEQ)       /* 3072  */
#define NCAT  (2*DSEQ)       /* 2048  */

// ---------------- scratch (device globals; no allocations allowed) ----------
__device__ bf16  g_xn  [MROWS*DSEQ];     // 32 MB  layernormed x, bf16
__device__ bf16  g_qkv [MROWS*NQKV];     // 96 MB  qkv projection, bf16
__device__ bf16  g_vc  [MROWS*NCAT];     // 64 MB  concat(v1,v2), bf16
__device__ bf16  g_win [NQKV*DSEQ];      // w_in bf16
__device__ bf16  g_wout[DSEQ*NCAT];      // w_out bf16
__device__ bf16  g_wm1a[HDIM*HDIM];      // w_m1a bf16
__device__ float g_aq[NB*NHEAD*NENC];    // mlp1(q)
__device__ float g_ak[NB*NHEAD*NENC];    // mlp1(k)
__device__ float g_cq[NB*NHEAD*HDIM];    // mlp2(q)
__device__ float g_ck[NB*NHEAD*HDIM];    // mlp2(k)

// ---------------- fp32 -> bf16 convert --------------------------------------
__global__ void f2bf_kernel(const float* __restrict__ in, bf16* __restrict__ out, int n) {
    int i = blockIdx.x * blockDim.x + threadIdx.x;
    if (i * 4 < n) {
        float4 v = reinterpret_cast<const float4*>(in)[i];
        bf16 o[4] = {__float2bfloat16(v.x), __float2bfloat16(v.y),
                     __float2bfloat16(v.z), __float2bfloat16(v.w)};
        reinterpret_cast<uint2*>(out)[i] = *reinterpret_cast<uint2*>(o);
    }
}

// ---------------- LayerNorm (row of 1024), write bf16 -----------------------
__global__ void ln_kernel(const float* __restrict__ x, const float* __restrict__ g,
                          const float* __restrict__ b, bf16* __restrict__ out) {
    int row = blockIdx.x;
    int t = threadIdx.x;                       // 256 threads, 4 elems each
    float4 v = reinterpret_cast<const float4*>(x + (size_t)row * DSEQ)[t];
    float s  = v.x + v.y + v.z + v.w;
    float s2 = v.x*v.x + v.y*v.y + v.z*v.z + v.w*v.w;
    __shared__ float red[2][8];
    #pragma unroll
    for (int o = 16; o > 0; o >>= 1) {
        s  += __shfl_down_sync(0xffffffffu, s,  o);
        s2 += __shfl_down_sync(0xffffffffu, s2, o);
    }
    if ((t & 31) == 0) { red[0][t >> 5] = s; red[1][t >> 5] = s2; }
    __syncthreads();
    float a = 0.f, a2 = 0.f;
    #pragma unroll
    for (int i = 0; i < 8; i++) { a += red[0][i]; a2 += red[1][i]; }
    float mean = a * (1.0f / DSEQ);
    float var  = a2 * (1.0f / DSEQ) - mean * mean;
    float rstd = rsqrtf(var + 1e-5f);
    float4 gg = reinterpret_cast<const float4*>(g)[t];
    float4 bb = reinterpret_cast<const float4*>(b)[t];
    bf16 o[4];
    o[0] = __float2bfloat16((v.x - mean) * rstd * gg.x + bb.x);
    o[1] = __float2bfloat16((v.y - mean) * rstd * gg.y + bb.y);
    o[2] = __float2bfloat16((v.z - mean) * rstd * gg.z + bb.z);
    o[3] = __float2bfloat16((v.w - mean) * rstd * gg.w + bb.w);
    reinterpret_cast<uint2*>(out + (size_t)row * DSEQ)[t] = *reinterpret_cast<uint2*>(o);
}

// ---------------- generic NT GEMM: C[M,N] = A[M,K] * B[N,K]^T + bias (+resid)
// EPI==0: store bf16(acc + bias)           (QKV projection)
// EPI==1: store fp32(acc + bias + resid)   (output projection + residual)
template<int EPI>
__global__ void __launch_bounds__(256, 2) gemm_nt(
    const bf16* __restrict__ A, const bf16* __restrict__ Bm, int K,
    const float* __restrict__ bias, const float* __restrict__ resid,
    void* __restrict__ C, int N) {

    constexpr int BM = 128, BN = 128, BK = 32, LDS = BK + 8;  // 40 (16B-mult rows)
    __shared__ __align__(16) char smem_raw[2 * BM * LDS * 2 + 2 * BN * LDS * 2]; // 40960 B
    bf16* sA = reinterpret_cast<bf16*>(smem_raw);
    bf16* sB = reinterpret_cast<bf16*>(smem_raw) + 2 * BM * LDS;
    float* sEpi = reinterpret_cast<float*>(smem_raw);  // reused after mainloop

    const int tid = threadIdx.x;
    const int warp = tid >> 5, lane = tid & 31;
    const int wm = warp >> 2, wn = warp & 3;  // 2x4 warp grid, warp tile 64x32
    const int rowA0 = blockIdx.y * BM;
    const int colB0 = blockIdx.x * BN;

    wmma::fragment<wmma::accumulator, 16, 16, 16, float> acc[4][2];
    #pragma unroll
    for (int fm = 0; fm < 4; fm++)
        #pragma unroll
        for (int fn = 0; fn < 2; fn++) wmma::fill_fragment(acc[fm][fn], 0.0f);

    uint4 ra[2], rb[2];
    auto gload = [&](int kt) {
        #pragma unroll
        for (int i = 0; i < 2; i++) {
            int v = tid + 256 * i;                // 512 16B-vectors per tile
            int r = v >> 2, c = (v & 3) * 8;
            ra[i] = *reinterpret_cast<const uint4*>(A + (size_t)(rowA0 + r) * K + kt * BK + c);
            rb[i] = *reinterpret_cast<const uint4*>(Bm + (size_t)(colB0 + r) * K + kt * BK + c);
        }
    };
    auto sstore = [&](int buf) {
        #pragma unroll
        for (int i = 0; i < 2; i++) {
            int v = tid + 256 * i;
            int r = v >> 2, c = (v & 3) * 8;
            *reinterpret_cast<uint4*>(sA + buf * BM * LDS + r * LDS + c) = ra[i];
            *reinterpret_cast<uint4*>(sB + buf * BN * LDS + r * LDS + c) = rb[i];
        }
    };

    const int KT = K / BK;
    gload(0); sstore(0); __syncthreads();
    for (int kt = 0; kt < KT; kt++) {
        int buf = kt & 1;
        if (kt + 1 < KT) gload(kt + 1);
        const bf16* pa = sA + buf * BM * LDS + wm * 64 * LDS;
        const bf16* pb = sB + buf * BN * LDS + wn * 32 * LDS;
        #pragma unroll
        for (int ks = 0; ks < 2; ks++) {
            wmma::fragment<wmma::matrix_a, 16, 16, 16, bf16, wmma::row_major> af[4];
            wmma::fragment<wmma::matrix_b, 16, 16, 16, bf16, wmma::col_major> bfr[2];
            #pragma unroll
            for (int fm = 0; fm < 4; fm++)
                wmma::load_matrix_sync(af[fm], pa + fm * 16 * LDS + ks * 16, LDS);
            #pragma unroll
            for (int fn = 0; fn < 2; fn++)
                wmma::load_matrix_sync(bfr[fn], pb + fn * 16 * LDS + ks * 16, LDS);
            #pragma unroll
            for (int fm = 0; fm < 4; fm++)
                #pragma unroll
                for (int fn = 0; fn < 2; fn++)
                    wmma::mma_sync(acc[fm][fn], af[fm], bfr[fn], acc[fm][fn]);
        }
        if (kt + 1 < KT) sstore(buf ^ 1);
        __syncthreads();
    }

    // epilogue: per-warp 16x36 fp32 staging (reuses tile smem; post-sync)
    float* epiW = sEpi + warp * (16 * 36);
    const int gr0 = rowA0 + wm * 64;
    const int gc0 = colB0 + wn * 32;
    const int col = lane;                 // 0..31
    float bs = bias[gc0 + col];
    #pragma unroll
    for (int fm = 0; fm < 4; fm++) {
        wmma::store_matrix_sync(epiW,      acc[fm][0], 36, wmma::mem_row_major);
        wmma::store_matrix_sync(epiW + 16, acc[fm][1], 36, wmma::mem_row_major);
        __syncwarp();
        #pragma unroll
        for (int rr = 0; rr < 16; rr++) {
            size_t grow = (size_t)(gr0 + fm * 16 + rr);
            float val = epiW[rr * 36 + col] + bs;
            if (EPI == 0) {
                reinterpret_cast<bf16*>(C)[grow * N + gc0 + col] = __float2bfloat16(val);
            } else {
                val += resid[grow * N + gc0 + col];
                reinterpret_cast<float*>(C)[grow * N + gc0 + col] = val;
            }
        }
        __syncwarp();
    }
}

// ---------------- mlp1: a[r] = w1b . relu(W1a * t_row + b1a) + b1b ----------
// rows r in [0, 131072): r = b*4096 + h*512 + n; t_row = 128 contiguous bf16 of
// qkv at ((b*512 + (r&4095)>>3)*3072 + ((r&7)<<7) + off)
__global__ void __launch_bounds__(256) mlp1_kernel(
    const bf16* __restrict__ qkv, int off,
    const float* __restrict__ b1a, const float* __restrict__ w1b,
    const float* __restrict__ b1b, float* __restrict__ aout) {

    extern __shared__ __align__(16) char dsm[];
    bf16*  sA   = reinterpret_cast<bf16*>(dsm);            // [128][136]
    bf16*  sB   = reinterpret_cast<bf16*>(dsm) + 128*136;  // [128][136]
    float* sAcc = reinterpret_cast<float*>(dsm);           // [128][132] (reuse)
    float* sb   = reinterpret_cast<float*>(dsm + 69632);   // b1a [128]
    float* sw   = sb + 128;                                // w1b [128]

    const int tid = threadIdx.x;
    const int warp = tid >> 5;
    const int wm = warp >> 2, wn = warp & 3;
    const int r0 = blockIdx.x * 128;

    if (tid < 128) { sb[tid] = b1a[tid]; sw[tid] = w1b[tid]; }
    #pragma unroll
    for (int i = 0; i < 8; i++) {          // A tile 128x128, 2048 16B-vectors
        int v = tid + 256 * i;
        int r = v >> 4, c = (v & 15) * 8;
        int gr = r0 + r;
        size_t base = ((size_t)(gr >> 12) * 512 + ((gr & 4095) >> 3)) * 3072
                    + ((gr & 7) << 7) + off;
        *reinterpret_cast<uint4*>(sA + r * 136 + c) =
            *reinterpret_cast<const uint4*>(qkv + base + c);
        *reinterpret_cast<uint4*>(sB + r * 136 + c) =
            *reinterpret_cast<const uint4*>(g_wm1a + r * 128 + c);
    }
    __syncthreads();

    wmma::fragment<wmma::accumulator, 16, 16, 16, float> acc[4][2];
    #pragma unroll
    for (int fm = 0; fm < 4; fm++)
        #pragma unroll
        for (int fn = 0; fn < 2; fn++) wmma::fill_fragment(acc[fm][fn], 0.0f);

    #pragma unroll
    for (int ks = 0; ks < 8; ks++) {
        wmma::fragment<wmma::matrix_a, 16, 16, 16, bf16, wmma::row_major> af[4];
        wmma::fragment<wmma::matrix_b, 16, 16, 16, bf16, wmma::col_major> bfr[2];
        #pragma unroll
        for (int fm = 0; fm < 4; fm++)
            wmma::load_matrix_sync(af[fm], sA + (wm * 64 + fm * 16) * 136 + ks * 16, 136);
        #pragma unroll
        for (int fn = 0; fn < 2; fn++)
            wmma::load_matrix_sync(bfr[fn], sB + (wn * 32 + fn * 16) * 136 + ks * 16, 136);
        #pragma unroll
        for (int fm = 0; fm < 4; fm++)
            #pragma unroll
            for (int fn = 0; fn < 2; fn++)
                wmma::mma_sync(acc[fm][fn], af[fm], bfr[fn], acc[fm][fn]);
    }
    __syncthreads();
    #pragma unroll
    for (int fm = 0; fm < 4; fm++)
        #pragma unroll
        for (int fn = 0; fn < 2; fn++)
            wmma::store_matrix_sync(sAcc + (wm * 64 + fm * 16) * 132 + wn * 32 + fn * 16,
                                    acc[fm][fn], 132, wmma::mem_row_major);
    __syncthreads();
    if (tid < 128) {
        float s = b1b[0];
        #pragma unroll 4
        for (int e = 0; e < 128; e++) {
            float v = sAcc[tid * 132 + e] + sb[e];
            s += fmaxf(v, 0.0f) * sw[e];
        }
        aout[r0 + tid] = s;
    }
}

// ---------------- mlp2: c[b,h,d] = relu(b2 + sum_n t[b,h,n,d]*w2[n]) --------
__global__ void mlp2_kernel(const bf16* __restrict__ qkv, int off,
                            const float* __restrict__ w2, const float* __restrict__ b2,
                            float* __restrict__ cout) {
    __shared__ float swv[512];
    __shared__ float part[4][128];
    int d = threadIdx.x;        // 128
    int ns = threadIdx.y;       // 4
    int h = blockIdx.x, b = blockIdx.y;
    for (int i = ns * 128 + d; i < 512; i += 512) swv[i] = w2[i];
    __syncthreads();
    float acc = 0.f;
    size_t rowbase = ((size_t)b * 512 + h * 64) * 3072 + off;
    #pragma unroll 4
    for (int nn = ns * 128; nn < (ns + 1) * 128; nn++) {
        size_t idx = rowbase + (size_t)(nn >> 3) * 3072 + ((nn & 7) << 7) + d;
        acc += __bfloat162float(qkv[idx]) * swv[nn];
    }
    part[ns][d] = acc;
    __syncthreads();
    if (ns == 0) {
        float s = part[0][d] + part[1][d] + part[2][d] + part[3][d] + b2[0];
        cout[((b * 8) + h) * 128 + d] = fmaxf(s, 0.0f);
    }
}

// ---------------- build concat(v1, v2) in [B*N, 2S] bf16 --------------------
__global__ void vcat_kernel(const bf16* __restrict__ qkv, bf16* __restrict__ vc,
                            const float* __restrict__ aq, const float* __restrict__ ak,
                            const float* __restrict__ cq, const float* __restrict__ ck) {
    int tid = blockIdx.x * blockDim.x + threadIdx.x;  // 4 elems each; 4,194,304 total
    int b  = tid >> 17;
    int ii = (tid & 131071) << 2;   // flat index within batch [0, 524288)
    int h = ii >> 16;
    int n = (ii >> 7) & 511;
    int d = ii & 127;
    int row = ii >> 10;
    int col = ii & 1023;
    const float scale = 1.0f / 256.0f;
    size_t qbase = ((size_t)b * 512 + row) * 3072;
    uint2 v4 = *reinterpret_cast<const uint2*>(qkv + qbase + 2048 + col);
    const bf16* vp = reinterpret_cast<const bf16*>(&v4);
    int bh = b * 8 + h;
    float a1 = aq[bh * 512 + n] * scale;
    float a2 = ak[bh * 512 + n] * scale;
    float4 c1 = *reinterpret_cast<const float4*>(ck + bh * 128 + d);
    float4 c2 = *reinterpret_cast<const float4*>(cq + bh * 128 + d);
    float cv1[4] = {c1.x, c1.y, c1.z, c1.w};
    float cv2[4] = {c2.x, c2.y, c2.z, c2.w};
    bf16 o1[4], o2[4];
    #pragma unroll
    for (int j = 0; j < 4; j++) {
        float vv = __bfloat162float(vp[j]);
        o1[j] = __float2bfloat16(a1 * cv1[j] * vv);
        o2[j] = __float2bfloat16(a2 * cv2[j] * vv);
    }
    size_t obase = ((size_t)b * 512 + row) * 2048;
    *reinterpret_cast<uint2*>(vc + obase + col)        = *reinterpret_cast<uint2*>(o1);
    *reinterpret_cast<uint2*>(vc + obase + 1024 + col) = *reinterpret_cast<uint2*>(o2);
}

// ---------------- launch --------------------------------------------------
extern "C" void kernel_launch(void* const* d_in, const int* in_sizes, int n_in,
                              void* d_out, int out_size) {
    const float* x     = (const float*)d_in[0];
    const float* ln_g  = (const float*)d_in[1];
    const float* ln_b  = (const float*)d_in[2];
    const float* w_in  = (const float*)d_in[3];
    const float* b_in  = (const float*)d_in[4];
    const float* w_m1a = (const float*)d_in[5];
    const float* b_m1a = (const float*)d_in[6];
    const float* w_m1b = (const float*)d_in[7];
    const float* b_m1b = (const float*)d_in[8];
    const float* w_m2  = (const float*)d_in[9];
    const float* b_m2  = (const float*)d_in[10];
    const float* w_out = (const float*)d_in[11];
    const float* b_out = (const float*)d_in[12];
    float* out = (float*)d_out;

    bf16 *xn, *qkv, *vc, *win, *wout, *wm1a;
    float *aq, *ak, *cq, *ck;
    cudaGetSymbolAddress((void**)&xn,   g_xn);
    cudaGetSymbolAddress((void**)&qkv,  g_qkv);
    cudaGetSymbolAddress((void**)&vc,   g_vc);
    cudaGetSymbolAddress((void**)&win,  g_win);
    cudaGetSymbolAddress((void**)&wout, g_wout);
    cudaGetSymbolAddress((void**)&wm1a, g_wm1a);
    cudaGetSymbolAddress((void**)&aq,   g_aq);
    cudaGetSymbolAddress((void**)&ak,   g_ak);
    cudaGetSymbolAddress((void**)&cq,   g_cq);
    cudaGetSymbolAddress((void**)&ck,   g_ck);

    cudaFuncSetAttribute(mlp1_kernel, cudaFuncAttributeMaxDynamicSharedMemorySize, 70656);

    // weight conversion (cheap, every call -> deterministic)
    f2bf_kernel<<<(NQKV * DSEQ / 4 + 255) / 256, 256>>>(w_in,  win,  NQKV * DSEQ);
    f2bf_kernel<<<(DSEQ * NCAT / 4 + 255) / 256, 256>>>(w_out, wout, DSEQ * NCAT);
    f2bf_kernel<<<(HDIM * HDIM / 4 + 255) / 256, 256>>>(w_m1a, wm1a, HDIM * HDIM);

    // 1) LayerNorm
    ln_kernel<<<MROWS, 256>>>(x, ln_g, ln_b, xn);
    // 2) QKV projection: [16384,1024] x [3072,1024]^T -> bf16 qkv
    gemm_nt<0><<<dim3(NQKV / 128, MROWS / 128), 256>>>(xn, win, DSEQ, b_in, nullptr, qkv, NQKV);
    // 3) mlp1 over q and k
    mlp1_kernel<<<1024, 256, 70656>>>(qkv, 0,    b_m1a, w_m1b, b_m1b, aq);
    mlp1_kernel<<<1024, 256, 70656>>>(qkv, 1024, b_m1a, w_m1b, b_m1b, ak);
    // 4) mlp2 over q and k
    mlp2_kernel<<<dim3(NHEAD, NB), dim3(128, 4)>>>(qkv, 0,    w_m2, b_m2, cq);
    mlp2_kernel<<<dim3(NHEAD, NB), dim3(128, 4)>>>(qkv, 1024, w_m2, b_m2, ck);
    // 5) rank-1 scaled V -> concat buffer
    vcat_kernel<<<16384, 256>>>(qkv, vc, aq, ak, cq, ck);
    // 6) output projection + bias + residual: [16384,2048] x [1024,2048]^T + x
    gemm_nt<1><<<dim3(DSEQ / 128, MROWS / 128), 256>>>(vc, wout, NCAT, b_out, x, out, DSEQ);
}

// round 3
// speedup vs baseline: 1.2110x; 1.2110x over previous
#include <cuda_runtime.h>
#include <cuda_bf16.h>
#include <mma.h>
#include <cstdint>

using namespace nvcuda;
typedef __nv_bfloat16 bf16;

#define NB    32
#define NENC  512
#define DSEQ  1024
#define NHEAD 8
#define HDIM  128
#define MROWS (NB*NENC)      /* 16384 */
#define NQKV  (3*DSEQ)       /* 3072  */
#define NCAT  (2*DSEQ)       /* 2048  */

// ---------------- scratch (device globals; no allocations allowed) ----------
__device__ bf16  g_xn  [MROWS*DSEQ];
__device__ bf16  g_qkv [MROWS*NQKV];
__device__ bf16  g_vc  [MROWS*NCAT];
__device__ bf16  g_win [NQKV*DSEQ];
__device__ bf16  g_wout[DSEQ*NCAT];
__device__ bf16  g_wm1a[HDIM*HDIM];
__device__ float g_aq[NB*NHEAD*NENC];
__device__ float g_ak[NB*NHEAD*NENC];
__device__ float g_cq[NB*NHEAD*HDIM];
__device__ float g_ck[NB*NHEAD*HDIM];

// ---------------- cp.async helpers ------------------------------------------
__device__ __forceinline__ uint32_t smem_u32(const void* p) {
    uint32_t a;
    asm("{ .reg .u64 t; cvta.to.shared.u64 t, %1; cvt.u32.u64 %0, t; }" : "=r"(a) : "l"(p));
    return a;
}
__device__ __forceinline__ void cp16(uint32_t dst, const void* src) {
    asm volatile("cp.async.cg.shared.global [%0], [%1], 16;" :: "r"(dst), "l"(src));
}
#define CP_COMMIT() asm volatile("cp.async.commit_group;" ::: "memory")
#define CP_WAIT0()  asm volatile("cp.async.wait_group 0;" ::: "memory")

// ======================= HMMA GEMM (cp.async, BK=64, 2 CTAs/SM) =============
// C[M,N] = A[M,K] * B[N,K]^T + bias (+resid). A,B bf16 K-major.
// EPI==0: store bf16(acc+bias).  EPI==1: store fp32(acc+bias+resid).
#define BM 128
#define BN 128
#define BKC 64
#define LDSK 72                    /* 144B rows: 16B-aligned, conflict-free   */
#define GEMM_SMEM (2 * (BM + BN) * LDSK * 2)   /* 73728 B */

template<int EPI>
__global__ void __launch_bounds__(256, 2) gemm_nt(
    const bf16* __restrict__ A, const bf16* __restrict__ Bm, int K,
    const float* __restrict__ bias, const float* __restrict__ resid,
    void* __restrict__ C, int N) {

    extern __shared__ __align__(16) char smem[];
    bf16* sA = reinterpret_cast<bf16*>(smem);             // [2][BM][LDSK]
    bf16* sB = sA + 2 * BM * LDSK;                        // [2][BN][LDSK]
    float* sEpi = reinterpret_cast<float*>(smem);         // reused post-loop
    const uint32_t sAu = smem_u32(sA);
    const uint32_t sBu = smem_u32(sB);

    const int tid  = threadIdx.x;
    const int warp = tid >> 5, lane = tid & 31;
    const int wm = warp >> 2, wn = warp & 3;              // 2x4 grid, 64x32 tiles
    const int rowA0 = blockIdx.y * BM;
    const int colB0 = blockIdx.x * BN;
    const int KT = K / BKC;

    // per-thread fixed load coords: 1024 16B-vectors per operand per stage
    const int lr = tid >> 3;             // row 0..31 base (stride 32)
    const int lc = tid & 7;              // 16B chunk 0..7

    auto load_stage = [&](int kt, int s) {
        const bf16* ga = A  + (size_t)(rowA0 + lr) * K + kt * BKC + lc * 8;
        const bf16* gb = Bm + (size_t)(colB0 + lr) * K + kt * BKC + lc * 8;
        uint32_t da = sAu + s * BM * LDSK * 2 + (lr * LDSK + lc * 8) * 2;
        uint32_t db = sBu + s * BN * LDSK * 2 + (lr * LDSK + lc * 8) * 2;
        #pragma unroll
        for (int i = 0; i < 4; i++) {
            cp16(da + i * 32 * LDSK * 2, ga + (size_t)i * 32 * K);
            cp16(db + i * 32 * LDSK * 2, gb + (size_t)i * 32 * K);
        }
    };

    wmma::fragment<wmma::accumulator, 16, 16, 16, float> acc[4][2];
    #pragma unroll
    for (int fm = 0; fm < 4; fm++)
        #pragma unroll
        for (int fn = 0; fn < 2; fn++) wmma::fill_fragment(acc[fm][fn], 0.0f);

    load_stage(0, 0); CP_COMMIT();

    for (int kt = 0; kt < KT; kt++) {
        const int s = kt & 1;
        CP_WAIT0();
        __syncthreads();
        if (kt + 1 < KT) { load_stage(kt + 1, s ^ 1); CP_COMMIT(); }

        const bf16* pa = sA + s * BM * LDSK + wm * 64 * LDSK;
        const bf16* pb = sB + s * BN * LDSK + wn * 32 * LDSK;
        #pragma unroll
        for (int ks = 0; ks < 4; ks++) {
            wmma::fragment<wmma::matrix_a, 16, 16, 16, bf16, wmma::row_major> af[4];
            wmma::fragment<wmma::matrix_b, 16, 16, 16, bf16, wmma::col_major> bfr[2];
            #pragma unroll
            for (int fm = 0; fm < 4; fm++)
                wmma::load_matrix_sync(af[fm], pa + fm * 16 * LDSK + ks * 16, LDSK);
            #pragma unroll
            for (int fn = 0; fn < 2; fn++)
                wmma::load_matrix_sync(bfr[fn], pb + fn * 16 * LDSK + ks * 16, LDSK);
            #pragma unroll
            for (int fm = 0; fm < 4; fm++)
                #pragma unroll
                for (int fn = 0; fn < 2; fn++)
                    wmma::mma_sync(acc[fm][fn], af[fm], bfr[fn], acc[fm][fn]);
        }
    }
    __syncthreads();

    // epilogue: per-warp 16x36 fp32 staging in reused smem, coalesced stores
    float* epiW = sEpi + warp * (16 * 36);
    const int gr0 = rowA0 + wm * 64;
    const int gc0 = colB0 + wn * 32;
    const int col = lane;
    float bs = bias[gc0 + col];
    #pragma unroll
    for (int fm = 0; fm < 4; fm++) {
        wmma::store_matrix_sync(epiW,      acc[fm][0], 36, wmma::mem_row_major);
        wmma::store_matrix_sync(epiW + 16, acc[fm][1], 36, wmma::mem_row_major);
        __syncwarp();
        #pragma unroll
        for (int rr = 0; rr < 16; rr++) {
            size_t grow = (size_t)(gr0 + fm * 16 + rr);
            float val = epiW[rr * 36 + col] + bs;
            if (EPI == 0) {
                reinterpret_cast<bf16*>(C)[grow * N + gc0 + col] = __float2bfloat16(val);
            } else {
                val += resid[grow * N + gc0 + col];
                reinterpret_cast<float*>(C)[grow * N + gc0 + col] = val;
            }
        }
        __syncwarp();
    }
}

// ---------------- fp32 -> bf16 convert --------------------------------------
__global__ void f2bf_kernel(const float* __restrict__ in, bf16* __restrict__ out, int n) {
    int i = blockIdx.x * blockDim.x + threadIdx.x;
    if (i * 4 < n) {
        float4 v = reinterpret_cast<const float4*>(in)[i];
        bf16 o[4] = {__float2bfloat16(v.x), __float2bfloat16(v.y),
                     __float2bfloat16(v.z), __float2bfloat16(v.w)};
        reinterpret_cast<uint2*>(out)[i] = *reinterpret_cast<uint2*>(o);
    }
}

// ---------------- LayerNorm (row of 1024), write bf16 -----------------------
__global__ void ln_kernel(const float* __restrict__ x, const float* __restrict__ g,
                          const float* __restrict__ b, bf16* __restrict__ out) {
    int row = blockIdx.x;
    int t = threadIdx.x;
    float4 v = reinterpret_cast<const float4*>(x + (size_t)row * DSEQ)[t];
    float s  = v.x + v.y + v.z + v.w;
    float s2 = v.x*v.x + v.y*v.y + v.z*v.z + v.w*v.w;
    __shared__ float red[2][8];
    #pragma unroll
    for (int o = 16; o > 0; o >>= 1) {
        s  += __shfl_down_sync(0xffffffffu, s,  o);
        s2 += __shfl_down_sync(0xffffffffu, s2, o);
    }
    if ((t & 31) == 0) { red[0][t >> 5] = s; red[1][t >> 5] = s2; }
    __syncthreads();
    float a = 0.f, a2 = 0.f;
    #pragma unroll
    for (int i = 0; i < 8; i++) { a += red[0][i]; a2 += red[1][i]; }
    float mean = a * (1.0f / DSEQ);
    float var  = a2 * (1.0f / DSEQ) - mean * mean;
    float rstd = rsqrtf(var + 1e-5f);
    float4 gg = reinterpret_cast<const float4*>(g)[t];
    float4 bb = reinterpret_cast<const float4*>(b)[t];
    bf16 o[4];
    o[0] = __float2bfloat16((v.x - mean) * rstd * gg.x + bb.x);
    o[1] = __float2bfloat16((v.y - mean) * rstd * gg.y + bb.y);
    o[2] = __float2bfloat16((v.z - mean) * rstd * gg.z + bb.z);
    o[3] = __float2bfloat16((v.w - mean) * rstd * gg.w + bb.w);
    reinterpret_cast<uint2*>(out + (size_t)row * DSEQ)[t] = *reinterpret_cast<uint2*>(o);
}

// ---------------- mlp1: a[r] = w1b . relu(W1a * t_row + b1a) + b1b ----------
__global__ void __launch_bounds__(256) mlp1_kernel(
    const bf16* __restrict__ qkv, int off,
    const float* __restrict__ b1a, const float* __restrict__ w1b,
    const float* __restrict__ b1b, float* __restrict__ aout) {

    extern __shared__ __align__(16) char dsm[];
    bf16*  sA   = reinterpret_cast<bf16*>(dsm);            // [128][136]
    bf16*  sB   = reinterpret_cast<bf16*>(dsm) + 128*136;  // [128][136]
    float* sAcc = reinterpret_cast<float*>(dsm);           // [128][132] (reuse)
    float* sb   = reinterpret_cast<float*>(dsm + 69632);
    float* sw   = sb + 128;

    const int tid = threadIdx.x;
    const int warp = tid >> 5;
    const int wm = warp >> 2, wn = warp & 3;
    const int r0 = blockIdx.x * 128;

    if (tid < 128) { sb[tid] = b1a[tid]; sw[tid] = w1b[tid]; }
    #pragma unroll
    for (int i = 0; i < 8; i++) {
        int v = tid + 256 * i;
        int r = v >> 4, c = (v & 15) * 8;
        int gr = r0 + r;
        size_t base = ((size_t)(gr >> 12) * 512 + ((gr & 4095) >> 3)) * 3072
                    + ((gr & 7) << 7) + off;
        *reinterpret_cast<uint4*>(sA + r * 136 + c) =
            *reinterpret_cast<const uint4*>(qkv + base + c);
        *reinterpret_cast<uint4*>(sB + r * 136 + c) =
            *reinterpret_cast<const uint4*>(g_wm1a + r * 128 + c);
    }
    __syncthreads();

    wmma::fragment<wmma::accumulator, 16, 16, 16, float> acc[4][2];
    #pragma unroll
    for (int fm = 0; fm < 4; fm++)
        #pragma unroll
        for (int fn = 0; fn < 2; fn++) wmma::fill_fragment(acc[fm][fn], 0.0f);

    #pragma unroll
    for (int ks = 0; ks < 8; ks++) {
        wmma::fragment<wmma::matrix_a, 16, 16, 16, bf16, wmma::row_major> af[4];
        wmma::fragment<wmma::matrix_b, 16, 16, 16, bf16, wmma::col_major> bfr[2];
        #pragma unroll
        for (int fm = 0; fm < 4; fm++)
            wmma::load_matrix_sync(af[fm], sA + (wm * 64 + fm * 16) * 136 + ks * 16, 136);
        #pragma unroll
        for (int fn = 0; fn < 2; fn++)
            wmma::load_matrix_sync(bfr[fn], sB + (wn * 32 + fn * 16) * 136 + ks * 16, 136);
        #pragma unroll
        for (int fm = 0; fm < 4; fm++)
            #pragma unroll
            for (int fn = 0; fn < 2; fn++)
                wmma::mma_sync(acc[fm][fn], af[fm], bfr[fn], acc[fm][fn]);
    }
    __syncthreads();
    #pragma unroll
    for (int fm = 0; fm < 4; fm++)
        #pragma unroll
        for (int fn = 0; fn < 2; fn++)
            wmma::store_matrix_sync(sAcc + (wm * 64 + fm * 16) * 132 + wn * 32 + fn * 16,
                                    acc[fm][fn], 132, wmma::mem_row_major);
    __syncthreads();
    if (tid < 128) {
        float s = b1b[0];
        #pragma unroll 4
        for (int e = 0; e < 128; e++) {
            float v = sAcc[tid * 132 + e] + sb[e];
            s += fmaxf(v, 0.0f) * sw[e];
        }
        aout[r0 + tid] = s;
    }
}

// ---------------- mlp2: c[b,h,d] = relu(b2 + sum_n t[b,h,n,d]*w2[n]) --------
__global__ void mlp2_kernel(const bf16* __restrict__ qkv, int off,
                            const float* __restrict__ w2, const float* __restrict__ b2,
                            float* __restrict__ cout) {
    __shared__ float swv[512];
    __shared__ float part[4][128];
    int d = threadIdx.x;
    int ns = threadIdx.y;
    int h = blockIdx.x, b = blockIdx.y;
    for (int i = ns * 128 + d; i < 512; i += 512) swv[i] = w2[i];
    __syncthreads();
    float acc = 0.f;
    size_t rowbase = ((size_t)b * 512 + h * 64) * 3072 + off;
    #pragma unroll 4
    for (int nn = ns * 128; nn < (ns + 1) * 128; nn++) {
        size_t idx = rowbase + (size_t)(nn >> 3) * 3072 + ((nn & 7) << 7) + d;
        acc += __bfloat162float(qkv[idx]) * swv[nn];
    }
    part[ns][d] = acc;
    __syncthreads();
    if (ns == 0) {
        float s = part[0][d] + part[1][d] + part[2][d] + part[3][d] + b2[0];
        cout[((b * 8) + h) * 128 + d] = fmaxf(s, 0.0f);
    }
}

// ---------------- build concat(v1, v2) in [B*N, 2S] bf16 --------------------
__global__ void vcat_kernel(const bf16* __restrict__ qkv, bf16* __restrict__ vc,
                            const float* __restrict__ aq, const float* __restrict__ ak,
                            const float* __restrict__ cq, const float* __restrict__ ck) {
    int tid = blockIdx.x * blockDim.x + threadIdx.x;
    int b  = tid >> 17;
    int ii = (tid & 131071) << 2;
    int h = ii >> 16;
    int n = (ii >> 7) & 511;
    int d = ii & 127;
    int row = ii >> 10;
    int col = ii & 1023;
    const float scale = 1.0f / 256.0f;
    size_t qbase = ((size_t)b * 512 + row) * 3072;
    uint2 v4 = *reinterpret_cast<const uint2*>(qkv + qbase + 2048 + col);
    const bf16* vp = reinterpret_cast<const bf16*>(&v4);
    int bh = b * 8 + h;
    float a1 = aq[bh * 512 + n] * scale;
    float a2 = ak[bh * 512 + n] * scale;
    float4 c1 = *reinterpret_cast<const float4*>(ck + bh * 128 + d);
    float4 c2 = *reinterpret_cast<const float4*>(cq + bh * 128 + d);
    float cv1[4] = {c1.x, c1.y, c1.z, c1.w};
    float cv2[4] = {c2.x, c2.y, c2.z, c2.w};
    bf16 o1[4], o2[4];
    #pragma unroll
    for (int j = 0; j < 4; j++) {
        float vv = __bfloat162float(vp[j]);
        o1[j] = __float2bfloat16(a1 * cv1[j] * vv);
        o2[j] = __float2bfloat16(a2 * cv2[j] * vv);
    }
    size_t obase = ((size_t)b * 512 + row) * 2048;
    *reinterpret_cast<uint2*>(vc + obase + col)        = *reinterpret_cast<uint2*>(o1);
    *reinterpret_cast<uint2*>(vc + obase + 1024 + col) = *reinterpret_cast<uint2*>(o2);
}

// ---------------- launch --------------------------------------------------
extern "C" void kernel_launch(void* const* d_in, const int* in_sizes, int n_in,
                              void* d_out, int out_size) {
    const float* x     = (const float*)d_in[0];
    const float* ln_g  = (const float*)d_in[1];
    const float* ln_b  = (const float*)d_in[2];
    const float* w_in  = (const float*)d_in[3];
    const float* b_in  = (const float*)d_in[4];
    const float* w_m1a = (const float*)d_in[5];
    const float* b_m1a = (const float*)d_in[6];
    const float* w_m1b = (const float*)d_in[7];
    const float* b_m1b = (const float*)d_in[8];
    const float* w_m2  = (const float*)d_in[9];
    const float* b_m2  = (const float*)d_in[10];
    const float* w_out = (const float*)d_in[11];
    const float* b_out = (const float*)d_in[12];
    float* out = (float*)d_out;

    bf16 *xn, *qkv, *vc, *win, *wout, *wm1a;
    float *aq, *ak, *cq, *ck;
    cudaGetSymbolAddress((void**)&xn,   g_xn);
    cudaGetSymbolAddress((void**)&qkv,  g_qkv);
    cudaGetSymbolAddress((void**)&vc,   g_vc);
    cudaGetSymbolAddress((void**)&win,  g_win);
    cudaGetSymbolAddress((void**)&wout, g_wout);
    cudaGetSymbolAddress((void**)&wm1a, g_wm1a);
    cudaGetSymbolAddress((void**)&aq,   g_aq);
    cudaGetSymbolAddress((void**)&ak,   g_ak);
    cudaGetSymbolAddress((void**)&cq,   g_cq);
    cudaGetSymbolAddress((void**)&ck,   g_ck);

    cudaFuncSetAttribute(mlp1_kernel, cudaFuncAttributeMaxDynamicSharedMemorySize, 70656);
    cudaFuncSetAttribute(gemm_nt<0>,  cudaFuncAttributeMaxDynamicSharedMemorySize, GEMM_SMEM);
    cudaFuncSetAttribute(gemm_nt<1>,  cudaFuncAttributeMaxDynamicSharedMemorySize, GEMM_SMEM);

    // weight conversion (cheap, deterministic each call)
    f2bf_kernel<<<(NQKV * DSEQ / 4 + 255) / 256, 256>>>(w_in,  win,  NQKV * DSEQ);
    f2bf_kernel<<<(DSEQ * NCAT / 4 + 255) / 256, 256>>>(w_out, wout, DSEQ * NCAT);
    f2bf_kernel<<<(HDIM * HDIM / 4 + 255) / 256, 256>>>(w_m1a, wm1a, HDIM * HDIM);

    // 1) LayerNorm
    ln_kernel<<<MROWS, 256>>>(x, ln_g, ln_b, xn);
    // 2) QKV projection: [16384,1024] x [3072,1024]^T -> bf16
    gemm_nt<0><<<dim3(NQKV / BN, MROWS / BM), 256, GEMM_SMEM>>>(xn, win, DSEQ, b_in, nullptr, qkv, NQKV);
    // 3) mlp1 over q and k
    mlp1_kernel<<<1024, 256, 70656>>>(qkv, 0,    b_m1a, w_m1b, b_m1b, aq);
    mlp1_kernel<<<1024, 256, 70656>>>(qkv, 1024, b_m1a, w_m1b, b_m1b, ak);
    // 4) mlp2 over q and k
    mlp2_kernel<<<dim3(NHEAD, NB), dim3(128, 4)>>>(qkv, 0,    w_m2, b_m2, cq);
    mlp2_kernel<<<dim3(NHEAD, NB), dim3(128, 4)>>>(qkv, 1024, w_m2, b_m2, ck);
    // 5) rank-1 scaled V -> concat buffer
    vcat_kernel<<<16384, 256>>>(qkv, vc, aq, ak, cq, ck);
    // 6) output projection + bias + residual
    gemm_nt<1><<<dim3(DSEQ / BN, MROWS / BM), 256, GEMM_SMEM>>>(vc, wout, NCAT, b_out, x, out, DSEQ);
}